// round 2
// baseline (speedup 1.0000x reference)
#include <cuda_runtime.h>
#include <math.h>

#define HH 192
#define WW 192
#define HW (HH*WW)
#define NBATCH 6
#define KC 400              // control points (20x20)
#define MM 403              // system size
#define NCOL 405            // augmented columns (matrix + 2 rhs)
#define SRIDE 416           // padded row stride (multiple of 4 -> 16B aligned rows)
#define LAMBDAV 100.0f
#define BIGV 1.0e8f
#define EPSV 1.0e-9f
#define STEPC (2.0f/191.0f)

// ---------------- device scratch (static allocation; no cudaMalloc) ----------------
__device__ float g_A[NBATCH * MM * SRIDE];   // ~4.0 MB augmented matrices
__device__ float g_warp[NBATCH * 5 * HW];    // coord_x, coord_y, delta_x, delta_y, mask
__device__ float g_src[NBATCH * KC * 2];     // warped src control coords
__device__ float g_sol[NBATCH * MM * 2];     // [wgt(400) ; aff(3)] x 2

// ---------------- Stage 1: backward warp of (coord, delta, mask) fields ----------------
__global__ void warp_kernel(const float* __restrict__ duv,
                            const float* __restrict__ uv,
                            float* __restrict__ outMask)
{
    int idx = blockIdx.x * blockDim.x + threadIdx.x;
    if (idx >= NBATCH * HW) return;
    int n = idx / HW;
    int p = idx - n * HW;

    float u = uv[idx * 2 + 0];
    float v = uv[idx * 2 + 1];
    float x = (u + 1.0f) * 0.5f * (float)(WW - 1);
    float y = (v + 1.0f) * 0.5f * (float)(HH - 1);
    float x0f = floorf(x), y0f = floorf(y);
    float wx = x - x0f, wy = y - y0f;
    int x0 = (int)x0f, y0 = (int)y0f;

    float w00 = (1.0f - wx) * (1.0f - wy);
    float w10 = wx * (1.0f - wy);
    float w01 = (1.0f - wx) * wy;
    float w11 = wx * wy;

    float acc0 = 0.f, acc1 = 0.f, acc2 = 0.f, acc3 = 0.f, acc4 = 0.f;

    const int dxs[4] = {0, 1, 0, 1};
    const int dys[4] = {0, 0, 1, 1};
    const float wts[4] = {w00, w10, w01, w11};

    #pragma unroll
    for (int c = 0; c < 4; ++c) {
        int xi = x0 + dxs[c];
        int yi = y0 + dys[c];
        if (xi >= 0 && xi < WW && yi >= 0 && yi < HH) {
            int q = yi * WW + xi;
            float dux = duv[q * 2 + 0];
            float duy = duv[q * 2 + 1];
            float val = (fabsf(dux) <= 1.0f && fabsf(duy) <= 1.0f) ? 1.0f : 0.0f;
            float gx = xi * STEPC - 1.0f;
            float gy = yi * STEPC - 1.0f;
            float w = wts[c];
            acc0 += gx * w;                  // coord field (xy), zero outside image
            acc1 += gy * w;
            acc2 += (dux - gx) * val * w;    // delta field
            acc3 += (duy - gy) * val * w;
            acc4 += val * w;                 // mask field
        }
    }

    float mk = (acc4 > 0.5f) ? 1.0f : 0.0f;
    float* Wp = g_warp + n * 5 * HW;
    Wp[0 * HW + p] = acc0;
    Wp[1 * HW + p] = acc1;
    Wp[2 * HW + p] = acc2;
    Wp[3 * HW + p] = acc3;
    Wp[4 * HW + p] = mk;
    outMask[idx] = mk;                       // mask_ output (n,1,h,w)
}

// ---------------- Stage 2: build augmented TPS systems ----------------
__global__ void build_kernel()
{
    int n  = blockIdx.x;
    int rb = blockIdx.y;          // row band
    int tid = threadIdx.x;

    __shared__ float s_sx[KC], s_sy[KC], s_m[KC], s_dx[KC], s_dy[KC];

    const float* Wp = g_warp + n * 5 * HW;
    for (int k = tid; k < KC; k += blockDim.x) {
        int a = k / 20, b = k - a * 20;
        int ii = __double2int_rn(a * (191.0 / 19.0));
        int jj = __double2int_rn(b * (191.0 / 19.0));
        int p = ii * WW + jj;
        float sx = Wp[p];
        float sy = Wp[HW + p];
        float m  = Wp[4 * HW + p];
        s_sx[k] = sx; s_sy[k] = sy; s_m[k] = m;
        s_dx[k] = jj * STEPC - 1.0f;
        s_dy[k] = ii * STEPC - 1.0f;
        if (rb == 0) {
            g_src[(n * KC + k) * 2 + 0] = sx;
            g_src[(n * KC + k) * 2 + 1] = sy;
        }
    }
    __syncthreads();

    float* A = g_A + n * MM * SRIDE;
    int r0 = rb * 51;
    int r1 = min(MM, r0 + 51);
    for (int i = r0; i < r1; ++i) {
        for (int j = tid; j < NCOL; j += blockDim.x) {
            float vout;
            if (i < KC) {
                if (j < KC) {
                    float dx = s_sx[i] - s_sx[j];
                    float dy = s_sy[i] - s_sy[j];
                    float r2 = dx * dx + dy * dy;
                    vout = 0.5f * r2 * __logf(r2 + EPSV);
                    if (i == j) vout += LAMBDAV + BIGV * (1.0f - s_m[i]);
                } else if (j == 400) vout = 1.0f;
                else if (j == 401) vout = s_sx[i];
                else if (j == 402) vout = s_sy[i];
                else if (j == 403) vout = s_dx[i];
                else               vout = s_dy[i];
            } else {
                if (j < KC) {
                    vout = (i == 400) ? 1.0f : ((i == 401) ? s_sx[j] : s_sy[j]);
                } else {
                    vout = 0.0f;
                }
            }
            A[i * SRIDE + j] = vout;
        }
    }
}

// ---------------- Stage 3: LU with partial pivoting + back-substitution ----------------
__global__ void __launch_bounds__(1024, 1) lu_kernel()
{
    int n = blockIdx.x;
    int tid = threadIdx.x;
    int lane = tid & 31;
    int wid = tid >> 5;

    float* A = g_A + n * MM * SRIDE;

    __shared__ float s_piv[416];
    __shared__ float s_rmax[32];
    __shared__ int   s_rrow[32];
    __shared__ int   s_prow;
    __shared__ float s_r[MM][2];

    for (int k = 0; k < MM; ++k) {
        // ---- pivot search on column k ----
        float best = -1.0f;
        int brow = k;
        for (int r = k + tid; r < MM; r += 1024) {
            float v = fabsf(A[r * SRIDE + k]);
            if (v > best) { best = v; brow = r; }
        }
        #pragma unroll
        for (int off = 16; off > 0; off >>= 1) {
            float ov = __shfl_down_sync(0xffffffffu, best, off);
            int   orow = __shfl_down_sync(0xffffffffu, brow, off);
            if (ov > best) { best = ov; brow = orow; }
        }
        if (lane == 0) { s_rmax[wid] = best; s_rrow[wid] = brow; }
        __syncthreads();
        if (wid == 0) {
            best = s_rmax[lane];
            brow = s_rrow[lane];
            #pragma unroll
            for (int off = 16; off > 0; off >>= 1) {
                float ov = __shfl_down_sync(0xffffffffu, best, off);
                int   orow = __shfl_down_sync(0xffffffffu, brow, off);
                if (ov > best) { best = ov; brow = orow; }
            }
            if (lane == 0) s_prow = brow;
        }
        __syncthreads();
        int pr = s_prow;

        // ---- row swap (cols k..404 only; left part never read again) ----
        if (pr != k) {
            for (int c = k + tid; c < NCOL; c += 1024) {
                float t = A[k * SRIDE + c];
                A[k * SRIDE + c] = A[pr * SRIDE + c];
                A[pr * SRIDE + c] = t;
            }
        }
        __syncthreads();

        // ---- pivot row to smem (including pad cols so float4 tail is safe) ----
        for (int c = k + tid; c < 408; c += 1024)
            s_piv[c - k] = A[k * SRIDE + c];
        __syncthreads();

        float pvinv = 1.0f / s_piv[0];

        // ---- trailing rank-1 update, float4-vectorized ----
        // head: cols k+1 .. head_end-1 (to 16B alignment); body: float4 chunks.
        int head_end = (k + 4) & ~3;          // first aligned col > k
        if (head_end > NCOL) head_end = NCOL;
        int tx = tid & 63;                    // 64 column threads
        int ty = tid >> 6;                    // 16 row groups
        for (int r = k + 1 + ty; r < MM; r += 16) {
            float m = A[r * SRIDE + k] * pvinv;   // col k is never overwritten -> race-free
            for (int c = k + 1 + tx; c < head_end; c += 64)
                A[r * SRIDE + c] -= m * s_piv[c - k];
            for (int c4 = head_end + 4 * tx; c4 < NCOL; c4 += 256) {
                float4 v = *(float4*)&A[r * SRIDE + c4];
                v.x -= m * s_piv[c4 + 0 - k];
                v.y -= m * s_piv[c4 + 1 - k];
                v.z -= m * s_piv[c4 + 2 - k];
                v.w -= m * s_piv[c4 + 3 - k];
                *(float4*)&A[r * SRIDE + c4] = v;
            }
        }
        __syncthreads();
    }

    // ---- back-substitution (U x = rhs, 2 rhs columns carried in 403/404) ----
    for (int j = tid; j < MM; j += 1024) {
        s_r[j][0] = A[j * SRIDE + 403];
        s_r[j][1] = A[j * SRIDE + 404];
    }
    __syncthreads();
    for (int k = MM - 1; k >= 0; --k) {
        if (tid == 0) {
            float d = A[k * SRIDE + k];
            s_r[k][0] /= d;
            s_r[k][1] /= d;
        }
        __syncthreads();
        float x0 = s_r[k][0], x1 = s_r[k][1];
        for (int j = tid; j < k; j += 1024) {
            float a = A[j * SRIDE + k];
            s_r[j][0] -= a * x0;
            s_r[j][1] -= a * x1;
        }
        __syncthreads();
    }
    for (int j = tid; j < MM; j += 1024) {
        g_sol[(n * MM + j) * 2 + 0] = s_r[j][0];
        g_sol[(n * MM + j) * 2 + 1] = s_r[j][1];
    }
}

// ---------------- Stage 4: TPS evaluation at 3 query grids + Jacobian + output ----------------
__global__ void __launch_bounds__(256) eval_kernel(float* __restrict__ outDef)
{
    int n = blockIdx.y;
    int p = blockIdx.x * blockDim.x + threadIdx.x;
    int tid = threadIdx.x;

    __shared__ float4 s_sw[KC];     // (src_x, src_y, wgt_x, wgt_y)
    __shared__ float s_aff[6];      // aff row-major (3,2)

    for (int k = tid; k < KC; k += blockDim.x) {
        float4 t;
        t.x = g_src[(n * KC + k) * 2 + 0];
        t.y = g_src[(n * KC + k) * 2 + 1];
        t.z = g_sol[(n * MM + k) * 2 + 0];
        t.w = g_sol[(n * MM + k) * 2 + 1];
        s_sw[k] = t;
    }
    if (tid < 6) s_aff[tid] = g_sol[(n * MM + 400) * 2 + tid];
    __syncthreads();

    const float* Wp = g_warp + n * 5 * HW;
    float q0x = Wp[p];
    float q0y = Wp[HW + p];
    float dlx = Wp[2 * HW + p];
    float dly = Wp[3 * HW + p];
    float mk  = Wp[4 * HW + p];
    float q1x = q0x + STEPC;
    float q2y = q0y + STEPC;

    float a0x = 0.f, a0y = 0.f, a1x = 0.f, a1y = 0.f, a2x = 0.f, a2y = 0.f;

    #pragma unroll 4
    for (int k = 0; k < KC; ++k) {
        float4 s = s_sw[k];
        float d0x = q0x - s.x;
        float d0y = q0y - s.y;
        float d1x = q1x - s.x;
        float d2y = q2y - s.y;
        float r0 = d0x * d0x + d0y * d0y;
        float r1 = d1x * d1x + d0y * d0y;
        float r2 = d0x * d0x + d2y * d2y;
        float u0 = 0.5f * r0 * __logf(r0 + EPSV);
        float u1 = 0.5f * r1 * __logf(r1 + EPSV);
        float u2 = 0.5f * r2 * __logf(r2 + EPSV);
        a0x = fmaf(u0, s.z, a0x);  a0y = fmaf(u0, s.w, a0y);
        a1x = fmaf(u1, s.z, a1x);  a1y = fmaf(u1, s.w, a1y);
        a2x = fmaf(u2, s.z, a2x);  a2y = fmaf(u2, s.w, a2y);
    }

    float c0x = a0x + s_aff[0] + s_aff[2] * q0x + s_aff[4] * q0y;
    float c0y = a0y + s_aff[1] + s_aff[3] * q0x + s_aff[5] * q0y;
    float c1x = a1x + s_aff[0] + s_aff[2] * q1x + s_aff[4] * q0y;
    float c1y = a1y + s_aff[1] + s_aff[3] * q1x + s_aff[5] * q0y;
    float c2x = a2x + s_aff[0] + s_aff[2] * q0x + s_aff[4] * q2y;
    float c2y = a2y + s_aff[1] + s_aff[3] * q0x + s_aff[5] * q2y;

    float ja = (c1x - c0x) / STEPC;   // a
    float jb = (c1y - c0y) / STEPC;   // b
    float jc = (c2x - c0x) / STEPC;   // c
    float jd = (c2y - c0y) / STEPC;   // d

    float dnx = ja * dlx + jc * dly;
    float dny = jb * dlx + jd * dly;

    int i = p / WW;
    int j = p - i * WW;
    float gx = j * STEPC - 1.0f;
    float gy = i * STEPC - 1.0f;
    float dfx = (gx + dnx) * mk - 2.0f * (1.0f - mk);
    float dfy = (gy + dny) * mk - 2.0f * (1.0f - mk);

    outDef[(n * HW + p) * 2 + 0] = dfx;
    outDef[(n * HW + p) * 2 + 1] = dfy;
}

// ---------------- launch ----------------
extern "C" void kernel_launch(void* const* d_in, const int* in_sizes, int n_in,
                              void* d_out, int out_size)
{
    const float* a0 = (const float*)d_in[0];
    const float* a1 = (const float*)d_in[1];
    const float* duv;
    const float* uv;
    if (in_sizes[0] == 2 * HW) { duv = a0; uv = a1; }
    else                        { duv = a1; uv = a0; }

    float* out = (float*)d_out;
    float* outDef  = out;                        // (N,H,W,2)
    float* outMask = out + NBATCH * HW * 2;      // (N,1,H,W)

    warp_kernel<<<(NBATCH * HW + 255) / 256, 256>>>(duv, uv, outMask);
    build_kernel<<<dim3(NBATCH, 8), 256>>>();
    lu_kernel<<<NBATCH, 1024>>>();
    eval_kernel<<<dim3(HW / 256, NBATCH), 256>>>(outDef);
}

// round 3
// speedup vs baseline: 3.0447x; 3.0447x over previous
#include <cuda_runtime.h>
#include <math.h>

#define HH 192
#define WW 192
#define HW (HH*WW)
#define NBATCH 6
#define KC 400              // control points (20x20)
#define MM 403              // system size
#define NCOL 405            // augmented columns (matrix + 2 rhs)
#define SRIDE 416           // padded row stride
#define NB 64               // LU panel width
#define LAMBDAV 100.0f
#define BIGV 1.0e8f
#define EPSV 1.0e-9f
#define STEPC (2.0f/191.0f)

// ---------------- device scratch ----------------
__device__ float g_A[NBATCH * MM * SRIDE];
__device__ float g_warp[NBATCH * 5 * HW];
__device__ float g_src[NBATCH * KC * 2];
__device__ float g_sol[NBATCH * MM * 2];
__device__ int   g_piv[NBATCH * 448];

// ---------------- Stage 1: backward warp ----------------
__global__ void warp_kernel(const float* __restrict__ duv,
                            const float* __restrict__ uv,
                            float* __restrict__ outMask)
{
    int idx = blockIdx.x * blockDim.x + threadIdx.x;
    if (idx >= NBATCH * HW) return;
    int n = idx / HW;
    int p = idx - n * HW;

    float u = uv[idx * 2 + 0];
    float v = uv[idx * 2 + 1];
    float x = (u + 1.0f) * 0.5f * (float)(WW - 1);
    float y = (v + 1.0f) * 0.5f * (float)(HH - 1);
    float x0f = floorf(x), y0f = floorf(y);
    float wx = x - x0f, wy = y - y0f;
    int x0 = (int)x0f, y0 = (int)y0f;

    float w00 = (1.0f - wx) * (1.0f - wy);
    float w10 = wx * (1.0f - wy);
    float w01 = (1.0f - wx) * wy;
    float w11 = wx * wy;

    float acc0 = 0.f, acc1 = 0.f, acc2 = 0.f, acc3 = 0.f, acc4 = 0.f;

    const int dxs[4] = {0, 1, 0, 1};
    const int dys[4] = {0, 0, 1, 1};
    const float wts[4] = {w00, w10, w01, w11};

    #pragma unroll
    for (int c = 0; c < 4; ++c) {
        int xi = x0 + dxs[c];
        int yi = y0 + dys[c];
        if (xi >= 0 && xi < WW && yi >= 0 && yi < HH) {
            int q = yi * WW + xi;
            float dux = duv[q * 2 + 0];
            float duy = duv[q * 2 + 1];
            float val = (fabsf(dux) <= 1.0f && fabsf(duy) <= 1.0f) ? 1.0f : 0.0f;
            float gx = xi * STEPC - 1.0f;
            float gy = yi * STEPC - 1.0f;
            float w = wts[c];
            acc0 += gx * w;
            acc1 += gy * w;
            acc2 += (dux - gx) * val * w;
            acc3 += (duy - gy) * val * w;
            acc4 += val * w;
        }
    }

    float mk = (acc4 > 0.5f) ? 1.0f : 0.0f;
    float* Wp = g_warp + n * 5 * HW;
    Wp[0 * HW + p] = acc0;
    Wp[1 * HW + p] = acc1;
    Wp[2 * HW + p] = acc2;
    Wp[3 * HW + p] = acc3;
    Wp[4 * HW + p] = mk;
    outMask[idx] = mk;
}

// ---------------- Stage 2: build augmented TPS systems ----------------
__global__ void build_kernel()
{
    int n  = blockIdx.x;
    int rb = blockIdx.y;
    int tid = threadIdx.x;

    __shared__ float s_sx[KC], s_sy[KC], s_m[KC], s_dx[KC], s_dy[KC];

    const float* Wp = g_warp + n * 5 * HW;
    for (int k = tid; k < KC; k += blockDim.x) {
        int a = k / 20, b = k - a * 20;
        int ii = __double2int_rn(a * (191.0 / 19.0));
        int jj = __double2int_rn(b * (191.0 / 19.0));
        int p = ii * WW + jj;
        float sx = Wp[p];
        float sy = Wp[HW + p];
        float m  = Wp[4 * HW + p];
        s_sx[k] = sx; s_sy[k] = sy; s_m[k] = m;
        s_dx[k] = jj * STEPC - 1.0f;
        s_dy[k] = ii * STEPC - 1.0f;
        if (rb == 0) {
            g_src[(n * KC + k) * 2 + 0] = sx;
            g_src[(n * KC + k) * 2 + 1] = sy;
        }
    }
    __syncthreads();

    float* A = g_A + n * MM * SRIDE;
    int r0 = rb * 51;
    int r1 = min(MM, r0 + 51);
    for (int i = r0; i < r1; ++i) {
        for (int j = tid; j < NCOL; j += blockDim.x) {
            float vout;
            if (i < KC) {
                if (j < KC) {
                    float dx = s_sx[i] - s_sx[j];
                    float dy = s_sy[i] - s_sy[j];
                    float r2 = dx * dx + dy * dy;
                    vout = 0.5f * r2 * __logf(r2 + EPSV);
                    if (i == j) vout += LAMBDAV + BIGV * (1.0f - s_m[i]);
                } else if (j == 400) vout = 1.0f;
                else if (j == 401) vout = s_sx[i];
                else if (j == 402) vout = s_sy[i];
                else if (j == 403) vout = s_dx[i];
                else               vout = s_dy[i];
            } else {
                if (j < KC) {
                    vout = (i == 400) ? 1.0f : ((i == 401) ? s_sx[j] : s_sy[j]);
                } else {
                    vout = 0.0f;
                }
            }
            A[i * SRIDE + j] = vout;
        }
    }
}

// ---------------- Stage 3a: panel factorization (in shared memory) ----------------
__global__ void __launch_bounds__(512, 1) panel_kernel(int k0, int nb)
{
    int n = blockIdx.x;
    int tid = threadIdx.x;
    int lane = tid & 31;
    int wid = tid >> 5;

    extern __shared__ float sP[];     // R rows x 65 (padded)
    __shared__ int s_prow;

    float* A = g_A + n * MM * SRIDE;
    int R = MM - k0;

    for (int idx = tid; idx < R * nb; idx += 512) {
        int r = idx / nb, c = idx - r * nb;
        sP[r * 65 + c] = A[(k0 + r) * SRIDE + k0 + c];
    }
    __syncthreads();

    for (int j = 0; j < nb; ++j) {
        // warp 0: pivot search + row swap within the panel
        if (wid == 0) {
            float best = -1.0f; int brow = j;
            for (int r = j + lane; r < R; r += 32) {
                float v = fabsf(sP[r * 65 + j]);
                if (v > best) { best = v; brow = r; }
            }
            #pragma unroll
            for (int off = 16; off > 0; off >>= 1) {
                float ov = __shfl_down_sync(0xffffffffu, best, off);
                int   orow = __shfl_down_sync(0xffffffffu, brow, off);
                if (ov > best) { best = ov; brow = orow; }
            }
            brow = __shfl_sync(0xffffffffu, brow, 0);
            if (brow != j) {
                for (int c = lane; c < nb; c += 32) {
                    float t = sP[j * 65 + c];
                    sP[j * 65 + c] = sP[brow * 65 + c];
                    sP[brow * 65 + c] = t;
                }
            }
            if (lane == 0) {
                s_prow = brow;  // (unused elsewhere; keeps ordering visible)
                g_piv[n * 448 + k0 + j] = k0 + brow;
            }
        }
        __syncthreads();

        float pivinv = 1.0f / sP[j * 65 + j];
        // rank-1 update: one warp owns each row band
        for (int r = j + 1 + wid; r < R; r += 16) {
            float m = sP[r * 65 + j] * pivinv;
            __syncwarp();
            for (int c = j + 1 + lane; c < nb; c += 32)
                sP[r * 65 + c] = fmaf(-m, sP[j * 65 + c], sP[r * 65 + c]);
            if (lane == 0) sP[r * 65 + j] = m;
        }
        __syncthreads();
    }

    for (int idx = tid; idx < R * nb; idx += 512) {
        int r = idx / nb, c = idx - r * nb;
        A[(k0 + r) * SRIDE + k0 + c] = sP[r * 65 + c];
    }
}

// ---------------- Stage 3b: apply pivots to trailing columns ----------------
__global__ void swap_kernel(int k0, int nb)
{
    int n = blockIdx.y;
    int col = k0 + nb + blockIdx.x * blockDim.x + threadIdx.x;
    if (col >= NCOL) return;
    float* A = g_A + n * MM * SRIDE;
    const int* piv = g_piv + n * 448;
    for (int j = 0; j < nb; ++j) {
        int rj = k0 + j;
        int pr = piv[rj];
        if (pr != rj) {
            float t = A[rj * SRIDE + col];
            A[rj * SRIDE + col] = A[pr * SRIDE + col];
            A[pr * SRIDE + col] = t;
        }
    }
}

// ---------------- Stage 3c: triangular solve U12 = L11^-1 * A12 ----------------
template<int TNB>
__global__ void __launch_bounds__(128) trisolve_kernel(int k0)
{
    int n = blockIdx.y;
    int tid = threadIdx.x;
    __shared__ float sL[TNB][TNB + 1];
    float* A = g_A + n * MM * SRIDE;

    for (int idx = tid; idx < TNB * TNB; idx += 128) {
        int r = idx / TNB, c = idx - r * TNB;
        sL[r][c] = A[(k0 + r) * SRIDE + k0 + c];
    }
    __syncthreads();

    int col = k0 + TNB + blockIdx.x * 128 + tid;
    if (col >= NCOL) return;

    float x[TNB];
    #pragma unroll
    for (int r = 0; r < TNB; ++r) x[r] = A[(k0 + r) * SRIDE + col];
    #pragma unroll
    for (int i = 0; i < TNB; ++i) {
        float xi = x[i];
        #pragma unroll
        for (int jj = i + 1; jj < TNB; ++jj)
            x[jj] = fmaf(-sL[jj][i], xi, x[jj]);
    }
    #pragma unroll
    for (int r = 0; r < TNB; ++r) A[(k0 + r) * SRIDE + col] = x[r];
}

// ---------------- Stage 3d: GEMM trailing update A22 -= L21 * U12 ----------------
__global__ void __launch_bounds__(256) gemm_kernel(int k0, int nb)
{
    int n = blockIdx.z;
    float* A = g_A + n * MM * SRIDE;
    int row0 = k0 + nb + blockIdx.x * 64;
    int col0 = k0 + nb + blockIdx.y * 64;

    __shared__ float As[64][65];   // L21 tile [m][k]
    __shared__ float Bs[64][65];   // U12 tile [k][c]

    int tid = threadIdx.x;
    for (int idx = tid; idx < 64 * 64; idx += 256) {
        int a = idx / 64, b = idx - a * 64;
        int r = row0 + a;
        As[a][b] = (r < MM && b < nb) ? A[r * SRIDE + k0 + b] : 0.0f;
        int c = col0 + b;
        Bs[a][b] = (a < nb && c < NCOL) ? A[(k0 + a) * SRIDE + c] : 0.0f;
    }
    __syncthreads();

    int tx = tid & 15, ty = tid >> 4;
    int m0 = ty * 4, c0 = tx * 4;

    float acc[4][4];
    #pragma unroll
    for (int i = 0; i < 4; ++i)
        #pragma unroll
        for (int j = 0; j < 4; ++j) acc[i][j] = 0.0f;

    #pragma unroll 8
    for (int kk = 0; kk < 64; ++kk) {
        float a0 = As[m0 + 0][kk], a1 = As[m0 + 1][kk];
        float a2 = As[m0 + 2][kk], a3 = As[m0 + 3][kk];
        float b0 = Bs[kk][c0 + 0], b1 = Bs[kk][c0 + 1];
        float b2 = Bs[kk][c0 + 2], b3 = Bs[kk][c0 + 3];
        acc[0][0] = fmaf(a0, b0, acc[0][0]); acc[0][1] = fmaf(a0, b1, acc[0][1]);
        acc[0][2] = fmaf(a0, b2, acc[0][2]); acc[0][3] = fmaf(a0, b3, acc[0][3]);
        acc[1][0] = fmaf(a1, b0, acc[1][0]); acc[1][1] = fmaf(a1, b1, acc[1][1]);
        acc[1][2] = fmaf(a1, b2, acc[1][2]); acc[1][3] = fmaf(a1, b3, acc[1][3]);
        acc[2][0] = fmaf(a2, b0, acc[2][0]); acc[2][1] = fmaf(a2, b1, acc[2][1]);
        acc[2][2] = fmaf(a2, b2, acc[2][2]); acc[2][3] = fmaf(a2, b3, acc[2][3]);
        acc[3][0] = fmaf(a3, b0, acc[3][0]); acc[3][1] = fmaf(a3, b1, acc[3][1]);
        acc[3][2] = fmaf(a3, b2, acc[3][2]); acc[3][3] = fmaf(a3, b3, acc[3][3]);
    }

    #pragma unroll
    for (int i = 0; i < 4; ++i) {
        int r = row0 + m0 + i;
        if (r >= MM) continue;
        #pragma unroll
        for (int j = 0; j < 4; ++j) {
            int c = col0 + c0 + j;
            if (c < NCOL) A[r * SRIDE + c] -= acc[i][j];
        }
    }
}

// ---------------- Stage 3e: back-substitution ----------------
__global__ void __launch_bounds__(256) backsub_kernel()
{
    int n = blockIdx.x;
    int tid = threadIdx.x;
    float* A = g_A + n * MM * SRIDE;

    __shared__ float s_r[MM][2];
    for (int j = tid; j < MM; j += 256) {
        s_r[j][0] = A[j * SRIDE + 403];
        s_r[j][1] = A[j * SRIDE + 404];
    }
    __syncthreads();
    for (int k = MM - 1; k >= 0; --k) {
        if (tid == 0) {
            float d = 1.0f / A[k * SRIDE + k];
            s_r[k][0] *= d;
            s_r[k][1] *= d;
        }
        __syncthreads();
        float x0 = s_r[k][0], x1 = s_r[k][1];
        for (int j = tid; j < k; j += 256) {
            float a = A[j * SRIDE + k];
            s_r[j][0] = fmaf(-a, x0, s_r[j][0]);
            s_r[j][1] = fmaf(-a, x1, s_r[j][1]);
        }
        __syncthreads();
    }
    for (int j = tid; j < MM; j += 256) {
        g_sol[(n * MM + j) * 2 + 0] = s_r[j][0];
        g_sol[(n * MM + j) * 2 + 1] = s_r[j][1];
    }
}

// ---------------- Stage 4: TPS evaluation + Jacobian + output ----------------
__global__ void __launch_bounds__(256) eval_kernel(float* __restrict__ outDef)
{
    int n = blockIdx.y;
    int p = blockIdx.x * blockDim.x + threadIdx.x;
    int tid = threadIdx.x;

    __shared__ float4 s_sw[KC];
    __shared__ float s_aff[6];

    for (int k = tid; k < KC; k += blockDim.x) {
        float4 t;
        t.x = g_src[(n * KC + k) * 2 + 0];
        t.y = g_src[(n * KC + k) * 2 + 1];
        t.z = g_sol[(n * MM + k) * 2 + 0];
        t.w = g_sol[(n * MM + k) * 2 + 1];
        s_sw[k] = t;
    }
    if (tid < 6) s_aff[tid] = g_sol[(n * MM + 400) * 2 + tid];
    __syncthreads();

    const float* Wp = g_warp + n * 5 * HW;
    float q0x = Wp[p];
    float q0y = Wp[HW + p];
    float dlx = Wp[2 * HW + p];
    float dly = Wp[3 * HW + p];
    float mk  = Wp[4 * HW + p];
    float q1x = q0x + STEPC;
    float q2y = q0y + STEPC;

    float a0x = 0.f, a0y = 0.f, a1x = 0.f, a1y = 0.f, a2x = 0.f, a2y = 0.f;

    #pragma unroll 4
    for (int k = 0; k < KC; ++k) {
        float4 s = s_sw[k];
        float d0x = q0x - s.x;
        float d0y = q0y - s.y;
        float d1x = q1x - s.x;
        float d2y = q2y - s.y;
        float r0 = d0x * d0x + d0y * d0y;
        float r1 = d1x * d1x + d0y * d0y;
        float r2 = d0x * d0x + d2y * d2y;
        float u0 = 0.5f * r0 * __logf(r0 + EPSV);
        float u1 = 0.5f * r1 * __logf(r1 + EPSV);
        float u2 = 0.5f * r2 * __logf(r2 + EPSV);
        a0x = fmaf(u0, s.z, a0x);  a0y = fmaf(u0, s.w, a0y);
        a1x = fmaf(u1, s.z, a1x);  a1y = fmaf(u1, s.w, a1y);
        a2x = fmaf(u2, s.z, a2x);  a2y = fmaf(u2, s.w, a2y);
    }

    float c0x = a0x + s_aff[0] + s_aff[2] * q0x + s_aff[4] * q0y;
    float c0y = a0y + s_aff[1] + s_aff[3] * q0x + s_aff[5] * q0y;
    float c1x = a1x + s_aff[0] + s_aff[2] * q1x + s_aff[4] * q0y;
    float c1y = a1y + s_aff[1] + s_aff[3] * q1x + s_aff[5] * q0y;
    float c2x = a2x + s_aff[0] + s_aff[2] * q0x + s_aff[4] * q2y;
    float c2y = a2y + s_aff[1] + s_aff[3] * q0x + s_aff[5] * q2y;

    float ja = (c1x - c0x) / STEPC;
    float jb = (c1y - c0y) / STEPC;
    float jc = (c2x - c0x) / STEPC;
    float jd = (c2y - c0y) / STEPC;

    float dnx = ja * dlx + jc * dly;
    float dny = jb * dlx + jd * dly;

    int i = p / WW;
    int j = p - i * WW;
    float gx = j * STEPC - 1.0f;
    float gy = i * STEPC - 1.0f;
    float dfx = (gx + dnx) * mk - 2.0f * (1.0f - mk);
    float dfy = (gy + dny) * mk - 2.0f * (1.0f - mk);

    outDef[(n * HW + p) * 2 + 0] = dfx;
    outDef[(n * HW + p) * 2 + 1] = dfy;
}

// ---------------- launch ----------------
extern "C" void kernel_launch(void* const* d_in, const int* in_sizes, int n_in,
                              void* d_out, int out_size)
{
    const float* a0 = (const float*)d_in[0];
    const float* a1 = (const float*)d_in[1];
    const float* duv;
    const float* uv;
    if (in_sizes[0] == 2 * HW) { duv = a0; uv = a1; }
    else                        { duv = a1; uv = a0; }

    float* out = (float*)d_out;
    float* outDef  = out;
    float* outMask = out + NBATCH * HW * 2;

    cudaFuncSetAttribute(panel_kernel,
                         cudaFuncAttributeMaxDynamicSharedMemorySize,
                         MM * 65 * (int)sizeof(float));

    warp_kernel<<<(NBATCH * HW + 255) / 256, 256>>>(duv, uv, outMask);
    build_kernel<<<dim3(NBATCH, 8), 256>>>();

    for (int k0 = 0; k0 < MM; k0 += NB) {
        int nb = (MM - k0 < NB) ? (MM - k0) : NB;
        int R = MM - k0;
        panel_kernel<<<NBATCH, 512, R * 65 * sizeof(float)>>>(k0, nb);
        int c2 = NCOL - (k0 + nb);
        if (c2 > 0) {
            swap_kernel<<<dim3((c2 + 255) / 256, NBATCH), 256>>>(k0, nb);
            if (nb == 64)
                trisolve_kernel<64><<<dim3((c2 + 127) / 128, NBATCH), 128>>>(k0);
            else
                trisolve_kernel<19><<<dim3((c2 + 127) / 128, NBATCH), 128>>>(k0);
            int r2 = MM - (k0 + nb);
            if (r2 > 0)
                gemm_kernel<<<dim3((r2 + 63) / 64, (c2 + 63) / 64, NBATCH), 256>>>(k0, nb);
        }
    }

    backsub_kernel<<<NBATCH, 256>>>();
    eval_kernel<<<dim3(HW / 256, NBATCH), 256>>>(outDef);
}